// round 15
// baseline (speedup 1.0000x reference)
#include <cuda_runtime.h>
#include <math.h>
#include <stdint.h>

#define SEQ   128
#define BATCH 128
#define DIM   1024
#define BD    (BATCH * DIM)

typedef unsigned long long ull;

// ---------------- packed f32x2 helpers (Blackwell FFMA2 path) ----------------
__device__ __forceinline__ ull pk2(float v) {
    ull r;
    asm("mov.b64 %0, {%1, %1};" : "=l"(r) : "f"(v));
    return r;
}
__device__ __forceinline__ void fma2(ull& d, ull a, ull b) {
    asm("fma.rn.f32x2 %0, %1, %2, %0;" : "+l"(d) : "l"(a), "l"(b));
}
__device__ __forceinline__ ull add2(ull a, ull b) {
    ull r;
    asm("add.rn.f32x2 %0, %1, %2;" : "=l"(r) : "l"(a), "l"(b));
    return r;
}
__device__ __forceinline__ float2 up2(ull v) {
    float2 f;
    asm("mov.b64 {%0, %1}, %2;" : "=f"(f.x), "=f"(f.y) : "l"(v));
    return f;
}
__device__ __forceinline__ void cp16(uint32_t dst, const void* src) {
    asm volatile("cp.async.cg.shared.global [%0], [%1], 16;" :: "r"(dst), "l"(src));
}
__device__ __forceinline__ void cp_commit() {
    asm volatile("cp.async.commit_group;");
}
__device__ __forceinline__ void cp_wait2() {
    asm volatile("cp.async.wait_group 2;");
}

// =============================================================================
// Kernel 1 (unchanged): xp[m, n] = sum_k X[m, k] * Wx[k, n] + b[n]
// Written directly into d_out; the scan overwrites it in place with h_t.
// =============================================================================
__global__ __launch_bounds__(256) void xp_kernel(
    const float* __restrict__ X, const float* __restrict__ Wx,
    const float* __restrict__ bias, float* __restrict__ out)
{
    __shared__ __align__(16) float As[16 * 68];
    __shared__ __align__(16) float Bs[16 * 64];

    const int tid = threadIdx.x;
    const int m0  = blockIdx.y * 64;
    const int n0  = blockIdx.x * 64;

    const int ar  = tid >> 2;
    const int ac4 = (tid & 3) * 4;
    const int br  = tid >> 4;
    const int bc4 = (tid & 15) * 4;

    const float* Aptr = X  + (size_t)(m0 + ar) * DIM + ac4;
    const float* Bptr = Wx + (size_t)br * DIM + n0 + bc4;

    float4 aR = *(const float4*)Aptr;
    float4 bR = *(const float4*)Bptr;

    const int tx = tid & 15;
    const int ty = tid >> 4;

    ull acc[4][2] = {};

    for (int k0 = 0; k0 < DIM; k0 += 16) {
        As[(ac4 + 0) * 68 + ar] = aR.x;
        As[(ac4 + 1) * 68 + ar] = aR.y;
        As[(ac4 + 2) * 68 + ar] = aR.z;
        As[(ac4 + 3) * 68 + ar] = aR.w;
        *(float4*)&Bs[br * 64 + bc4] = bR;
        __syncthreads();

        if (k0 + 16 < DIM) {
            aR = *(const float4*)(Aptr + k0 + 16);
            bR = *(const float4*)(Bptr + (size_t)(k0 + 16) * DIM);
        }

#pragma unroll
        for (int kk = 0; kk < 16; kk++) {
            float4 av = *(const float4*)&As[kk * 68 + ty * 4];
            ulonglong2 bv = *(const ulonglong2*)&Bs[kk * 64 + tx * 4];
            ull a0 = pk2(av.x), a1 = pk2(av.y);
            ull a2 = pk2(av.z), a3 = pk2(av.w);
            fma2(acc[0][0], a0, bv.x); fma2(acc[0][1], a0, bv.y);
            fma2(acc[1][0], a1, bv.x); fma2(acc[1][1], a1, bv.y);
            fma2(acc[2][0], a2, bv.x); fma2(acc[2][1], a2, bv.y);
            fma2(acc[3][0], a3, bv.x); fma2(acc[3][1], a3, bv.y);
        }
        __syncthreads();
    }

#pragma unroll
    for (int r = 0; r < 4; r++) {
        const int m = m0 + ty * 4 + r;
        float* orow = out + (size_t)m * DIM + n0 + tx * 4;
#pragma unroll
        for (int p = 0; p < 2; p++) {
            float2 v = up2(acc[r][p]);
            const int n = n0 + tx * 4 + p * 2;
            v.x += bias[n];
            v.y += bias[n + 1];
            *(float2*)(orow + p * 2) = v;
        }
    }
}

// =============================================================================
// Kernel 2 (rewritten): one scan step, h_t = tanh(xp_t + Hprev @ Wh), in place.
//
// Grid 128 blocks (16 n x 8 m), 256 threads = 4 split-K quarters x 2 warps.
// Each quarter computes the 16x64 tile over K/4 = 256:
//   - H quarter-slice staged ONCE into smem, k-transposed + f32x2-duplicated
//     (no pk2 in the hot loop): Hs2[k][m] as ull, row stride 18 (bank spread).
//   - Wh streamed via cp.async, BK=16, 4 slots, depth-3 prefetch, 1 bar/iter.
//   - inner kk: 2x LDS.128 (H, broadcast) + 1x LDS.128 (Wh) + 8x FFMA2.
// Epilogue: quarters 1-3 dump accs to smem (reusing Wh slots 0-2 of q0, safe
// after the it=15 barrier), quarter 0 reduces in fixed order, adds xp, tanh.
// =============================================================================
#define H_ULL_STRIDE 18
#define H_Q_ULLS     (256 * H_ULL_STRIDE)           // per-quarter Hs2 ulls
#define H_BYTES      (4 * H_Q_ULLS * 8)             // 147456
#define W_Q_FLOATS   (4 * 16 * 64)                  // 4 slots per quarter
#define W_BYTES      (4 * W_Q_FLOATS * 4)           // 65536
#define SMEM_STEP    (H_BYTES + W_BYTES)            // 212992 (208KB)

__global__ __launch_bounds__(256) void step_kernel(
    const float* __restrict__ Hprev, const float* __restrict__ Wh,
    float* __restrict__ outT)
{
    extern __shared__ __align__(16) char smem[];
    ull*   Hs2 = (ull*)smem;
    float* Ws  = (float*)(smem + H_BYTES);
    ull*   Red = (ull*)Ws;   // reuses q0's Wh slots 0-2 (12KB) in the epilogue

    const int tid = threadIdx.x;
    const int q   = tid >> 6;      // split-K quarter 0..3
    const int tq  = tid & 63;      // thread within quarter
    const int m0  = blockIdx.y * 16;
    const int n0  = blockIdx.x * 64;
    const int kq  = q * 256;       // this quarter's k base

    ull*   Hq = Hs2 + q * H_Q_ULLS;
    float* Wq = Ws  + q * W_Q_FLOATS;
    const uint32_t wq_addr = (uint32_t)__cvta_generic_to_shared(Wq);

    // ---- Wh stage issue: 16 k-rows x 64 n floats (4KB) per stage ----
    const float* WhBase = Wh + (size_t)kq * DIM + n0;
    const int wrow = tq >> 4;              // base row 0..3 (rows wrow, wrow+4, ...)
    const int wc4  = (tq & 15) * 4;        // float col offset 0..60

#define ISSUE_STAGE(s) do {                                                    \
        const int _slot = (s) & 3;                                            \
        const float* _src = WhBase + (size_t)((s) * 16 + wrow) * DIM + wc4;   \
        uint32_t _dst = wq_addr + (uint32_t)((_slot * 16 + wrow) * 64 + wc4) * 4; \
        cp16(_dst,                  _src);                                     \
        cp16(_dst + 4 * 64 * 4,     _src + (size_t)4 * DIM);                   \
        cp16(_dst + 8 * 64 * 4,     _src + (size_t)8 * DIM);                   \
        cp16(_dst + 12 * 64 * 4,    _src + (size_t)12 * DIM);                  \
    } while (0)

    ISSUE_STAGE(0); cp_commit();
    ISSUE_STAGE(1); cp_commit();
    ISSUE_STAGE(2); cp_commit();

    // ---- stage H quarter-slice: transposed + f32x2-duplicated ----
    {
        const int m  = tq >> 2;            // 0..15
        const int kg = (tq & 3) * 4;       // 0,4,8,12
        const float* hsrc = Hprev + (size_t)(m0 + m) * DIM + kq + kg;
#pragma unroll
        for (int j = 0; j < 16; j++) {
            float4 hv = *(const float4*)(hsrc + j * 16);
            const int kl = kg + j * 16;
            Hq[(kl + 0) * H_ULL_STRIDE + m] = pk2(hv.x);
            Hq[(kl + 1) * H_ULL_STRIDE + m] = pk2(hv.y);
            Hq[(kl + 2) * H_ULL_STRIDE + m] = pk2(hv.z);
            Hq[(kl + 3) * H_ULL_STRIDE + m] = pk2(hv.w);
        }
    }

    const int ty = tq >> 4;                // 0..3 -> rows m0 + 4*ty ..
    const int tx = tq & 15;                // 0..15 -> cols n0 + 4*tx ..
    ull acc[4][2] = {};

    for (int it = 0; it < 16; ++it) {
        cp_wait2();                        // stage `it` resident
        __syncthreads();                   // visible to all; slot (it-1)&3 free
        if (it + 3 < 16) ISSUE_STAGE(it + 3);   // writes slot (it-1)&3 — safe
        cp_commit();                       // keep group count uniform

        const ull*   hbase = Hq + (it * 16) * H_ULL_STRIDE + 4 * ty;
        const float* wbase = Wq + (it & 3) * (16 * 64) + tx * 4;
#pragma unroll
        for (int kk = 0; kk < 16; kk++) {
            ulonglong2 h01 = *(const ulonglong2*)(hbase + kk * H_ULL_STRIDE);
            ulonglong2 h23 = *(const ulonglong2*)(hbase + kk * H_ULL_STRIDE + 2);
            ulonglong2 w   = *(const ulonglong2*)(wbase + kk * 64);
            fma2(acc[0][0], h01.x, w.x); fma2(acc[0][1], h01.x, w.y);
            fma2(acc[1][0], h01.y, w.x); fma2(acc[1][1], h01.y, w.y);
            fma2(acc[2][0], h23.x, w.x); fma2(acc[2][1], h23.x, w.y);
            fma2(acc[3][0], h23.y, w.x); fma2(acc[3][1], h23.y, w.y);
        }
    }
#undef ISSUE_STAGE

    // ---- split-K reduction + xp + tanh ----
    if (q) {
        ull* r = Red + ((size_t)(q - 1) * 64 + tq) * 8;
#pragma unroll
        for (int rr = 0; rr < 4; rr++) {
            r[rr * 2]     = acc[rr][0];
            r[rr * 2 + 1] = acc[rr][1];
        }
    }
    __syncthreads();
    if (q == 0) {
        float* orow0 = outT + (size_t)(m0 + 4 * ty) * DIM + n0 + tx * 4;
#pragma unroll
        for (int rr = 0; rr < 4; rr++) {
            ull a0 = acc[rr][0], a1 = acc[rr][1];
#pragma unroll
            for (int qq = 0; qq < 3; qq++) {
                const ull* r = Red + ((size_t)qq * 64 + tq) * 8 + rr * 2;
                a0 = add2(a0, r[0]);
                a1 = add2(a1, r[1]);
            }
            float2 v0 = up2(a0), v1 = up2(a1);
            float* orow = orow0 + (size_t)rr * DIM;
            float4 xv = *(const float4*)orow;
            float4 res;
            res.x = tanhf(v0.x + xv.x);
            res.y = tanhf(v0.y + xv.y);
            res.z = tanhf(v1.x + xv.z);
            res.w = tanhf(v1.y + xv.w);
            *(float4*)orow = res;
        }
    }
}

// =============================================================================
// Launch: xp GEMM once, then 128 dependent steps chained through d_out.
// =============================================================================
extern "C" void kernel_launch(void* const* d_in, const int* in_sizes, int n_in,
                              void* d_out, int out_size)
{
    const float* x  = (const float*)d_in[0];  // [SEQ, BATCH, DIM]
    const float* h0 = (const float*)d_in[1];  // [BATCH, DIM]
    const float* Wx = (const float*)d_in[2];  // [DIM, DIM]
    const float* Wh = (const float*)d_in[3];  // [DIM, DIM]
    const float* b  = (const float*)d_in[4];  // [DIM]
    float* out = (float*)d_out;               // [SEQ, BATCH, DIM]

    cudaFuncSetAttribute(step_kernel,
                         cudaFuncAttributeMaxDynamicSharedMemorySize, SMEM_STEP);

    xp_kernel<<<dim3(DIM / 64, (SEQ * BATCH) / 64), 256>>>(x, Wx, b, out);

    for (int t = 0; t < SEQ; t++) {
        const float* hprev = (t == 0) ? h0 : out + (size_t)(t - 1) * BD;
        step_kernel<<<dim3(DIM / 64, BATCH / 16), 256, SMEM_STEP>>>(
            hprev, Wh, out + (size_t)t * BD);
    }
}

// round 16
// speedup vs baseline: 1.0015x; 1.0015x over previous
#include <cuda_runtime.h>
#include <math.h>
#include <stdint.h>

#define SEQ   128
#define BATCH 128
#define DIM   1024
#define BD    (BATCH * DIM)

typedef unsigned long long ull;

// ---------------- packed f32x2 helpers (Blackwell FFMA2 path) ----------------
__device__ __forceinline__ ull pk2(float v) {
    ull r;
    asm("mov.b64 %0, {%1, %1};" : "=l"(r) : "f"(v));
    return r;
}
__device__ __forceinline__ void fma2(ull& d, ull a, ull b) {
    asm("fma.rn.f32x2 %0, %1, %2, %0;" : "+l"(d) : "l"(a), "l"(b));
}
__device__ __forceinline__ ull add2(ull a, ull b) {
    ull r;
    asm("add.rn.f32x2 %0, %1, %2;" : "=l"(r) : "l"(a), "l"(b));
    return r;
}
__device__ __forceinline__ float2 up2(ull v) {
    float2 f;
    asm("mov.b64 {%0, %1}, %2;" : "=f"(f.x), "=f"(f.y) : "l"(v));
    return f;
}
__device__ __forceinline__ void cp16(uint32_t dst, const void* src) {
    asm volatile("cp.async.cg.shared.global [%0], [%1], 16;" :: "r"(dst), "l"(src));
}
__device__ __forceinline__ void cp_commit() {
    asm volatile("cp.async.commit_group;");
}
__device__ __forceinline__ void cp_wait2() {
    asm volatile("cp.async.wait_group 2;");
}

// =============================================================================
// Kernel 1 (unchanged): xp[m, n] = sum_k X[m, k] * Wx[k, n] + b[n]
// Written directly into d_out; the scan overwrites it in place with h_t.
// =============================================================================
__global__ __launch_bounds__(256) void xp_kernel(
    const float* __restrict__ X, const float* __restrict__ Wx,
    const float* __restrict__ bias, float* __restrict__ out)
{
    __shared__ __align__(16) float As[16 * 68];
    __shared__ __align__(16) float Bs[16 * 64];

    const int tid = threadIdx.x;
    const int m0  = blockIdx.y * 64;
    const int n0  = blockIdx.x * 64;

    const int ar  = tid >> 2;
    const int ac4 = (tid & 3) * 4;
    const int br  = tid >> 4;
    const int bc4 = (tid & 15) * 4;

    const float* Aptr = X  + (size_t)(m0 + ar) * DIM + ac4;
    const float* Bptr = Wx + (size_t)br * DIM + n0 + bc4;

    float4 aR = *(const float4*)Aptr;
    float4 bR = *(const float4*)Bptr;

    const int tx = tid & 15;
    const int ty = tid >> 4;

    ull acc[4][2] = {};

    for (int k0 = 0; k0 < DIM; k0 += 16) {
        As[(ac4 + 0) * 68 + ar] = aR.x;
        As[(ac4 + 1) * 68 + ar] = aR.y;
        As[(ac4 + 2) * 68 + ar] = aR.z;
        As[(ac4 + 3) * 68 + ar] = aR.w;
        *(float4*)&Bs[br * 64 + bc4] = bR;
        __syncthreads();

        if (k0 + 16 < DIM) {
            aR = *(const float4*)(Aptr + k0 + 16);
            bR = *(const float4*)(Bptr + (size_t)(k0 + 16) * DIM);
        }

#pragma unroll
        for (int kk = 0; kk < 16; kk++) {
            float4 av = *(const float4*)&As[kk * 68 + ty * 4];
            ulonglong2 bv = *(const ulonglong2*)&Bs[kk * 64 + tx * 4];
            ull a0 = pk2(av.x), a1 = pk2(av.y);
            ull a2 = pk2(av.z), a3 = pk2(av.w);
            fma2(acc[0][0], a0, bv.x); fma2(acc[0][1], a0, bv.y);
            fma2(acc[1][0], a1, bv.x); fma2(acc[1][1], a1, bv.y);
            fma2(acc[2][0], a2, bv.x); fma2(acc[2][1], a2, bv.y);
            fma2(acc[3][0], a3, bv.x); fma2(acc[3][1], a3, bv.y);
        }
        __syncthreads();
    }

#pragma unroll
    for (int r = 0; r < 4; r++) {
        const int m = m0 + ty * 4 + r;
        float* orow = out + (size_t)m * DIM + n0 + tx * 4;
#pragma unroll
        for (int p = 0; p < 2; p++) {
            float2 v = up2(acc[r][p]);
            const int n = n0 + tx * 4 + p * 2;
            v.x += bias[n];
            v.y += bias[n + 1];
            *(float2*)(orow + p * 2) = v;
        }
    }
}

// =============================================================================
// Kernel 2 (rewritten): one scan step, h_t = tanh(xp_t + Hprev @ Wh), in place.
//
// Grid 128 blocks (16 n x 8 m), 256 threads = 4 split-K quarters x 2 warps.
// Each quarter computes the 16x64 tile over K/4 = 256:
//   - H quarter-slice staged ONCE into smem, k-transposed + f32x2-duplicated
//     (no pk2 in the hot loop): Hs2[k][m] as ull, row stride 18 (bank spread).
//   - Wh streamed via cp.async, BK=16, 4 slots, depth-3 prefetch, 1 bar/iter.
//   - inner kk: 2x LDS.128 (H, broadcast) + 1x LDS.128 (Wh) + 8x FFMA2.
// Epilogue: quarters 1-3 dump accs to smem (reusing Wh slots 0-2 of q0, safe
// after the it=15 barrier), quarter 0 reduces in fixed order, adds xp, tanh.
// =============================================================================
#define H_ULL_STRIDE 18
#define H_Q_ULLS     (256 * H_ULL_STRIDE)           // per-quarter Hs2 ulls
#define H_BYTES      (4 * H_Q_ULLS * 8)             // 147456
#define W_Q_FLOATS   (4 * 16 * 64)                  // 4 slots per quarter
#define W_BYTES      (4 * W_Q_FLOATS * 4)           // 65536
#define SMEM_STEP    (H_BYTES + W_BYTES)            // 212992 (208KB)

__global__ __launch_bounds__(256) void step_kernel(
    const float* __restrict__ Hprev, const float* __restrict__ Wh,
    float* __restrict__ outT)
{
    extern __shared__ __align__(16) char smem[];
    ull*   Hs2 = (ull*)smem;
    float* Ws  = (float*)(smem + H_BYTES);
    ull*   Red = (ull*)Ws;   // reuses q0's Wh slots 0-2 (12KB) in the epilogue

    const int tid = threadIdx.x;
    const int q   = tid >> 6;      // split-K quarter 0..3
    const int tq  = tid & 63;      // thread within quarter
    const int m0  = blockIdx.y * 16;
    const int n0  = blockIdx.x * 64;
    const int kq  = q * 256;       // this quarter's k base

    ull*   Hq = Hs2 + q * H_Q_ULLS;
    float* Wq = Ws  + q * W_Q_FLOATS;
    const uint32_t wq_addr = (uint32_t)__cvta_generic_to_shared(Wq);

    // ---- Wh stage issue: 16 k-rows x 64 n floats (4KB) per stage ----
    const float* WhBase = Wh + (size_t)kq * DIM + n0;
    const int wrow = tq >> 4;              // base row 0..3 (rows wrow, wrow+4, ...)
    const int wc4  = (tq & 15) * 4;        // float col offset 0..60

#define ISSUE_STAGE(s) do {                                                    \
        const int _slot = (s) & 3;                                            \
        const float* _src = WhBase + (size_t)((s) * 16 + wrow) * DIM + wc4;   \
        uint32_t _dst = wq_addr + (uint32_t)((_slot * 16 + wrow) * 64 + wc4) * 4; \
        cp16(_dst,                  _src);                                     \
        cp16(_dst + 4 * 64 * 4,     _src + (size_t)4 * DIM);                   \
        cp16(_dst + 8 * 64 * 4,     _src + (size_t)8 * DIM);                   \
        cp16(_dst + 12 * 64 * 4,    _src + (size_t)12 * DIM);                  \
    } while (0)

    ISSUE_STAGE(0); cp_commit();
    ISSUE_STAGE(1); cp_commit();
    ISSUE_STAGE(2); cp_commit();

    // ---- stage H quarter-slice: transposed + f32x2-duplicated ----
    {
        const int m  = tq >> 2;            // 0..15
        const int kg = (tq & 3) * 4;       // 0,4,8,12
        const float* hsrc = Hprev + (size_t)(m0 + m) * DIM + kq + kg;
#pragma unroll
        for (int j = 0; j < 16; j++) {
            float4 hv = *(const float4*)(hsrc + j * 16);
            const int kl = kg + j * 16;
            Hq[(kl + 0) * H_ULL_STRIDE + m] = pk2(hv.x);
            Hq[(kl + 1) * H_ULL_STRIDE + m] = pk2(hv.y);
            Hq[(kl + 2) * H_ULL_STRIDE + m] = pk2(hv.z);
            Hq[(kl + 3) * H_ULL_STRIDE + m] = pk2(hv.w);
        }
    }

    const int ty = tq >> 4;                // 0..3 -> rows m0 + 4*ty ..
    const int tx = tq & 15;                // 0..15 -> cols n0 + 4*tx ..
    ull acc[4][2] = {};

    for (int it = 0; it < 16; ++it) {
        cp_wait2();                        // stage `it` resident
        __syncthreads();                   // visible to all; slot (it-1)&3 free
        if (it + 3 < 16) ISSUE_STAGE(it + 3);   // writes slot (it-1)&3 — safe
        cp_commit();                       // keep group count uniform

        const ull*   hbase = Hq + (it * 16) * H_ULL_STRIDE + 4 * ty;
        const float* wbase = Wq + (it & 3) * (16 * 64) + tx * 4;
#pragma unroll
        for (int kk = 0; kk < 16; kk++) {
            ulonglong2 h01 = *(const ulonglong2*)(hbase + kk * H_ULL_STRIDE);
            ulonglong2 h23 = *(const ulonglong2*)(hbase + kk * H_ULL_STRIDE + 2);
            ulonglong2 w   = *(const ulonglong2*)(wbase + kk * 64);
            fma2(acc[0][0], h01.x, w.x); fma2(acc[0][1], h01.x, w.y);
            fma2(acc[1][0], h01.y, w.x); fma2(acc[1][1], h01.y, w.y);
            fma2(acc[2][0], h23.x, w.x); fma2(acc[2][1], h23.x, w.y);
            fma2(acc[3][0], h23.y, w.x); fma2(acc[3][1], h23.y, w.y);
        }
    }
#undef ISSUE_STAGE

    // ---- split-K reduction + xp + tanh ----
    if (q) {
        ull* r = Red + ((size_t)(q - 1) * 64 + tq) * 8;
#pragma unroll
        for (int rr = 0; rr < 4; rr++) {
            r[rr * 2]     = acc[rr][0];
            r[rr * 2 + 1] = acc[rr][1];
        }
    }
    __syncthreads();
    if (q == 0) {
        float* orow0 = outT + (size_t)(m0 + 4 * ty) * DIM + n0 + tx * 4;
#pragma unroll
        for (int rr = 0; rr < 4; rr++) {
            ull a0 = acc[rr][0], a1 = acc[rr][1];
#pragma unroll
            for (int qq = 0; qq < 3; qq++) {
                const ull* r = Red + ((size_t)qq * 64 + tq) * 8 + rr * 2;
                a0 = add2(a0, r[0]);
                a1 = add2(a1, r[1]);
            }
            float2 v0 = up2(a0), v1 = up2(a1);
            float* orow = orow0 + (size_t)rr * DIM;
            float4 xv = *(const float4*)orow;
            float4 res;
            res.x = tanhf(v0.x + xv.x);
            res.y = tanhf(v0.y + xv.y);
            res.z = tanhf(v1.x + xv.z);
            res.w = tanhf(v1.y + xv.w);
            *(float4*)orow = res;
        }
    }
}

// =============================================================================
// Launch: xp GEMM once, then 128 dependent steps chained through d_out.
// =============================================================================
extern "C" void kernel_launch(void* const* d_in, const int* in_sizes, int n_in,
                              void* d_out, int out_size)
{
    const float* x  = (const float*)d_in[0];  // [SEQ, BATCH, DIM]
    const float* h0 = (const float*)d_in[1];  // [BATCH, DIM]
    const float* Wx = (const float*)d_in[2];  // [DIM, DIM]
    const float* Wh = (const float*)d_in[3];  // [DIM, DIM]
    const float* b  = (const float*)d_in[4];  // [DIM]
    float* out = (float*)d_out;               // [SEQ, BATCH, DIM]

    cudaFuncSetAttribute(step_kernel,
                         cudaFuncAttributeMaxDynamicSharedMemorySize, SMEM_STEP);

    xp_kernel<<<dim3(DIM / 64, (SEQ * BATCH) / 64), 256>>>(x, Wx, b, out);

    for (int t = 0; t < SEQ; t++) {
        const float* hprev = (t == 0) ? h0 : out + (size_t)(t - 1) * BD;
        step_kernel<<<dim3(DIM / 64, BATCH / 16), 256, SMEM_STEP>>>(
            hprev, Wh, out + (size_t)t * BD);
    }
}

// round 17
// speedup vs baseline: 1.0301x; 1.0286x over previous
#include <cuda_runtime.h>
#include <math.h>
#include <stdint.h>

#define SEQ   128
#define BATCH 128
#define DIM   1024
#define BD    (BATCH * DIM)

typedef unsigned long long ull;

// ---------------- packed f32x2 helpers (Blackwell FFMA2 path) ----------------
__device__ __forceinline__ ull pk2(float v) {
    ull r;
    asm("mov.b64 %0, {%1, %1};" : "=l"(r) : "f"(v));
    return r;
}
__device__ __forceinline__ void fma2(ull& d, ull a, ull b) {
    asm("fma.rn.f32x2 %0, %1, %2, %0;" : "+l"(d) : "l"(a), "l"(b));
}
__device__ __forceinline__ ull add2(ull a, ull b) {
    ull r;
    asm("add.rn.f32x2 %0, %1, %2;" : "=l"(r) : "l"(a), "l"(b));
    return r;
}
__device__ __forceinline__ float2 up2(ull v) {
    float2 f;
    asm("mov.b64 {%0, %1}, %2;" : "=f"(f.x), "=f"(f.y) : "l"(v));
    return f;
}
__device__ __forceinline__ void cp16(uint32_t dst, const void* src) {
    asm volatile("cp.async.cg.shared.global [%0], [%1], 16;" :: "r"(dst), "l"(src));
}
__device__ __forceinline__ void cp_commit() {
    asm volatile("cp.async.commit_group;");
}
__device__ __forceinline__ void cp_wait0() {
    asm volatile("cp.async.wait_group 0;");
}

// =============================================================================
// Kernel 1 (unchanged): xp[m, n] = sum_k X[m, k] * Wx[k, n] + b[n]
// Written directly into d_out; the scan overwrites it in place with h_t.
// =============================================================================
__global__ __launch_bounds__(256) void xp_kernel(
    const float* __restrict__ X, const float* __restrict__ Wx,
    const float* __restrict__ bias, float* __restrict__ out)
{
    __shared__ __align__(16) float As[16 * 68];
    __shared__ __align__(16) float Bs[16 * 64];

    const int tid = threadIdx.x;
    const int m0  = blockIdx.y * 64;
    const int n0  = blockIdx.x * 64;

    const int ar  = tid >> 2;
    const int ac4 = (tid & 3) * 4;
    const int br  = tid >> 4;
    const int bc4 = (tid & 15) * 4;

    const float* Aptr = X  + (size_t)(m0 + ar) * DIM + ac4;
    const float* Bptr = Wx + (size_t)br * DIM + n0 + bc4;

    float4 aR = *(const float4*)Aptr;
    float4 bR = *(const float4*)Bptr;

    const int tx = tid & 15;
    const int ty = tid >> 4;

    ull acc[4][2] = {};

    for (int k0 = 0; k0 < DIM; k0 += 16) {
        As[(ac4 + 0) * 68 + ar] = aR.x;
        As[(ac4 + 1) * 68 + ar] = aR.y;
        As[(ac4 + 2) * 68 + ar] = aR.z;
        As[(ac4 + 3) * 68 + ar] = aR.w;
        *(float4*)&Bs[br * 64 + bc4] = bR;
        __syncthreads();

        if (k0 + 16 < DIM) {
            aR = *(const float4*)(Aptr + k0 + 16);
            bR = *(const float4*)(Bptr + (size_t)(k0 + 16) * DIM);
        }

#pragma unroll
        for (int kk = 0; kk < 16; kk++) {
            float4 av = *(const float4*)&As[kk * 68 + ty * 4];
            ulonglong2 bv = *(const ulonglong2*)&Bs[kk * 64 + tx * 4];
            ull a0 = pk2(av.x), a1 = pk2(av.y);
            ull a2 = pk2(av.z), a3 = pk2(av.w);
            fma2(acc[0][0], a0, bv.x); fma2(acc[0][1], a0, bv.y);
            fma2(acc[1][0], a1, bv.x); fma2(acc[1][1], a1, bv.y);
            fma2(acc[2][0], a2, bv.x); fma2(acc[2][1], a2, bv.y);
            fma2(acc[3][0], a3, bv.x); fma2(acc[3][1], a3, bv.y);
        }
        __syncthreads();
    }

#pragma unroll
    for (int r = 0; r < 4; r++) {
        const int m = m0 + ty * 4 + r;
        float* orow = out + (size_t)m * DIM + n0 + tx * 4;
#pragma unroll
        for (int p = 0; p < 2; p++) {
            float2 v = up2(acc[r][p]);
            const int n = n0 + tx * 4 + p * 2;
            v.x += bias[n];
            v.y += bias[n + 1];
            *(float2*)(orow + p * 2) = v;
        }
    }
}

// =============================================================================
// Kernel 2: one scan step, h_t = tanh(xp_t + Hprev @ Wh), in place.
//
// Grid 128 blocks (16 n x 8 m), 512 threads = 8 split-K eighths x 2 warps
// (16 warps/SM -> 4 warps per SMSP for latency hiding).
// Each eighth computes the 16x64 tile over K/8 = 128:
//   - H eighth-slice staged ONCE, k-transposed + f32x2-duplicated.
//   - Wh streamed via cp.async: BK=16, 2-slot ring, depth-1 prefetch,
//     wait_group(0) + one barrier per iteration (8 iters/step).
//   - inner kk: 2x LDS.128 (H, broadcast) + 1x LDS.128 (Wh) + 8x FFMA2.
// Epilogue: eighths 1-7 dump accs into their OWN Wh slot-0 (dead after the
// it=6 read; last compute uses slot 1), lane-contiguous; eighth 0 reduces in
// fixed order, adds xp, applies tanh.
// =============================================================================
#define H_ULL_STRIDE 18
#define H_Q_ULLS     (128 * H_ULL_STRIDE)           // per-eighth Hs2 ulls (2304)
#define H_BYTES      (8 * H_Q_ULLS * 8)             // 147456
#define W_Q_FLOATS   (2 * 16 * 64)                  // 2 slots per eighth (2048)
#define W_BYTES      (8 * W_Q_FLOATS * 4)           // 65536
#define SMEM_STEP    (H_BYTES + W_BYTES)            // 212992 (208KB)

__global__ __launch_bounds__(512) void step_kernel(
    const float* __restrict__ Hprev, const float* __restrict__ Wh,
    float* __restrict__ outT)
{
    extern __shared__ __align__(16) char smem[];
    ull*   Hs2 = (ull*)smem;
    float* Ws  = (float*)(smem + H_BYTES);

    const int tid = threadIdx.x;
    const int q   = tid >> 6;      // split-K eighth 0..7
    const int tq  = tid & 63;      // thread within eighth
    const int m0  = blockIdx.y * 16;
    const int n0  = blockIdx.x * 64;
    const int kq  = q * 128;       // this eighth's k base

    ull*   Hq = Hs2 + q * H_Q_ULLS;
    float* Wq = Ws  + q * W_Q_FLOATS;
    const uint32_t wq_addr = (uint32_t)__cvta_generic_to_shared(Wq);

    // ---- Wh stage issue: 16 k-rows x 64 n floats (4KB) per stage ----
    const float* WhBase = Wh + (size_t)kq * DIM + n0;
    const int wrow = tq >> 4;              // base row 0..3 (rows wrow, wrow+4, ...)
    const int wc4  = (tq & 15) * 4;        // float col offset 0..60

#define ISSUE_STAGE(s) do {                                                    \
        const int _slot = (s) & 1;                                            \
        const float* _src = WhBase + (size_t)((s) * 16 + wrow) * DIM + wc4;   \
        uint32_t _dst = wq_addr + (uint32_t)((_slot * 16 + wrow) * 64 + wc4) * 4; \
        cp16(_dst,                  _src);                                     \
        cp16(_dst + 4 * 64 * 4,     _src + (size_t)4 * DIM);                   \
        cp16(_dst + 8 * 64 * 4,     _src + (size_t)8 * DIM);                   \
        cp16(_dst + 12 * 64 * 4,    _src + (size_t)12 * DIM);                  \
    } while (0)

    ISSUE_STAGE(0); cp_commit();

    // ---- stage H eighth-slice: transposed + f32x2-duplicated ----
    {
        const int m  = tq >> 2;            // 0..15
        const int kg = (tq & 3) * 4;       // 0,4,8,12
        const float* hsrc = Hprev + (size_t)(m0 + m) * DIM + kq + kg;
#pragma unroll
        for (int j = 0; j < 8; j++) {
            float4 hv = *(const float4*)(hsrc + j * 16);
            const int kl = kg + j * 16;
            Hq[(kl + 0) * H_ULL_STRIDE + m] = pk2(hv.x);
            Hq[(kl + 1) * H_ULL_STRIDE + m] = pk2(hv.y);
            Hq[(kl + 2) * H_ULL_STRIDE + m] = pk2(hv.z);
            Hq[(kl + 3) * H_ULL_STRIDE + m] = pk2(hv.w);
        }
    }

    const int ty = tq >> 4;                // 0..3 -> rows m0 + 4*ty ..
    const int tx = tq & 15;                // 0..15 -> cols n0 + 4*tx ..
    ull acc[4][2] = {};

    for (int it = 0; it < 8; ++it) {
        cp_wait0();                        // stage `it` resident
        __syncthreads();                   // all finished stage it-1 compute
        if (it + 1 < 8) {                  // prefetch next stage into the slot
            ISSUE_STAGE(it + 1);           // freed by the barrier above
            cp_commit();
        }

        const ull*   hbase = Hq + (it * 16) * H_ULL_STRIDE + 4 * ty;
        const float* wbase = Wq + (it & 1) * (16 * 64) + tx * 4;
#pragma unroll
        for (int kk = 0; kk < 16; kk++) {
            ulonglong2 h01 = *(const ulonglong2*)(hbase + kk * H_ULL_STRIDE);
            ulonglong2 h23 = *(const ulonglong2*)(hbase + kk * H_ULL_STRIDE + 2);
            ulonglong2 w   = *(const ulonglong2*)(wbase + kk * 64);
            fma2(acc[0][0], h01.x, w.x); fma2(acc[0][1], h01.x, w.y);
            fma2(acc[1][0], h01.y, w.x); fma2(acc[1][1], h01.y, w.y);
            fma2(acc[2][0], h23.x, w.x); fma2(acc[2][1], h23.x, w.y);
            fma2(acc[3][0], h23.y, w.x); fma2(acc[3][1], h23.y, w.y);
        }
    }
#undef ISSUE_STAGE

    // ---- split-K reduction + xp + tanh ----
    // Eighths 1-7 dump partials into their OWN Wh slot-0 region (dead: last
    // slot-0 read was iteration 6; iteration 7 computed from slot 1).
    // Layout lane-contiguous: Red_q[(rr*2+p)*64 + tq] -> conflict-free STS.64.
    if (q) {
        ull* r = (ull*)Wq;
#pragma unroll
        for (int rr = 0; rr < 4; rr++) {
            r[(rr * 2 + 0) * 64 + tq] = acc[rr][0];
            r[(rr * 2 + 1) * 64 + tq] = acc[rr][1];
        }
    }
    __syncthreads();
    if (q == 0) {
        float* orow0 = outT + (size_t)(m0 + 4 * ty) * DIM + n0 + tx * 4;
#pragma unroll
        for (int rr = 0; rr < 4; rr++) {
            ull a0 = acc[rr][0], a1 = acc[rr][1];
#pragma unroll
            for (int qq = 1; qq < 8; qq++) {
                const ull* r = (const ull*)(Ws + qq * W_Q_FLOATS);
                a0 = add2(a0, r[(rr * 2 + 0) * 64 + tq]);
                a1 = add2(a1, r[(rr * 2 + 1) * 64 + tq]);
            }
            float2 v0 = up2(a0), v1 = up2(a1);
            float* orow = orow0 + (size_t)rr * DIM;
            float4 xv = *(const float4*)orow;
            float4 res;
            res.x = tanhf(v0.x + xv.x);
            res.y = tanhf(v0.y + xv.y);
            res.z = tanhf(v1.x + xv.z);
            res.w = tanhf(v1.y + xv.w);
            *(float4*)orow = res;
        }
    }
}

// =============================================================================
// Launch: xp GEMM once, then 128 dependent steps chained through d_out.
// =============================================================================
extern "C" void kernel_launch(void* const* d_in, const int* in_sizes, int n_in,
                              void* d_out, int out_size)
{
    const float* x  = (const float*)d_in[0];  // [SEQ, BATCH, DIM]
    const float* h0 = (const float*)d_in[1];  // [BATCH, DIM]
    const float* Wx = (const float*)d_in[2];  // [DIM, DIM]
    const float* Wh = (const float*)d_in[3];  // [DIM, DIM]
    const float* b  = (const float*)d_in[4];  // [DIM]
    float* out = (float*)d_out;               // [SEQ, BATCH, DIM]

    cudaFuncSetAttribute(step_kernel,
                         cudaFuncAttributeMaxDynamicSharedMemorySize, SMEM_STEP);

    xp_kernel<<<dim3(DIM / 64, (SEQ * BATCH) / 64), 256>>>(x, Wx, b, out);

    for (int t = 0; t < SEQ; t++) {
        const float* hprev = (t == 0) ? h0 : out + (size_t)(t - 1) * BD;
        step_kernel<<<dim3(DIM / 64, BATCH / 16), 512, SMEM_STEP>>>(
            hprev, Wh, out + (size_t)t * BD);
    }
}